// round 14
// baseline (speedup 1.0000x reference)
#include <cuda_runtime.h>
#include <cuda.h>
#include <cuda_bf16.h>

#define NBATCH 8
#define SEQ 2048
#define DM 512
#define NH 8
#define DKV 64
#define ROWS (NBATCH*SEQ)
#define HID_ELEMS (ROWS*DM)
#define PB_ELEMS (NH*SEQ*SEQ)
#define WELEMS (DM*DM)
#define LOG2E 1.4426950408889634f

__device__ float g_bias[NH*4096];
__device__ float g_bias2[NH*4096];
__device__ __nv_bfloat16 g_ahi[HID_ELEMS];
__device__ __nv_bfloat16 g_alo[HID_ELEMS];
__device__ __nv_bfloat16 g_whi[4*WELEMS];    // [z][k][n]
__device__ __nv_bfloat16 g_wlo[4*WELEMS];
__device__ __nv_bfloat16 g_qkvh[3*HID_ELEMS];
__device__ __nv_bfloat16 g_qkvl[3*HID_ELEMS];

// ---------------- helpers ----------------
__device__ __forceinline__ unsigned smem_u32(const void* p) {
    unsigned a;
    asm("{ .reg .u64 t; cvta.to.shared.u64 t, %1; cvt.u32.u64 %0, t; }" : "=r"(a) : "l"(p));
    return a;
}
__device__ __forceinline__ unsigned sw128(unsigned x) { return x ^ ((x >> 3) & 0x70u); }
__device__ __forceinline__ void ldsm4(unsigned* r, unsigned addr) {
    asm volatile("ldmatrix.sync.aligned.m8n8.x4.shared.b16 {%0,%1,%2,%3}, [%4];"
        : "=r"(r[0]), "=r"(r[1]), "=r"(r[2]), "=r"(r[3]) : "r"(addr));
}
__device__ __forceinline__ void ldsm4t(unsigned* r, unsigned addr) {
    asm volatile("ldmatrix.sync.aligned.m8n8.x4.trans.shared.b16 {%0,%1,%2,%3}, [%4];"
        : "=r"(r[0]), "=r"(r[1]), "=r"(r[2]), "=r"(r[3]) : "r"(addr));
}
__device__ __forceinline__ void mma16816(float* c, const unsigned* a, unsigned b0, unsigned b1) {
    asm volatile("mma.sync.aligned.m16n8k16.row.col.f32.bf16.bf16.f32 "
        "{%0,%1,%2,%3}, {%4,%5,%6,%7}, {%8,%9}, {%0,%1,%2,%3};"
        : "+f"(c[0]), "+f"(c[1]), "+f"(c[2]), "+f"(c[3])
        : "r"(a[0]), "r"(a[1]), "r"(a[2]), "r"(a[3]), "r"(b0), "r"(b1));
}
__device__ __forceinline__ void tma2(unsigned dst, const CUtensorMap* m, int x, int y, unsigned mbar) {
    asm volatile("cp.async.bulk.tensor.2d.shared::cta.global.tile.mbarrier::complete_tx::bytes "
        "[%0], [%1, {%2, %3}], [%4];" :: "r"(dst), "l"(m), "r"(x), "r"(y), "r"(mbar) : "memory");
}
#define MBAR_INIT(a,c)   asm volatile("mbarrier.init.shared.b64 [%0], %1;" :: "r"((unsigned)(a)), "r"((unsigned)(c)) : "memory")
#define MBAR_EXPECT(a,b) asm volatile("mbarrier.arrive.expect_tx.shared.b64 _, [%0], %1;" :: "r"((unsigned)(a)), "r"((unsigned)(b)) : "memory")
__device__ __forceinline__ void mbar_wait(unsigned a, unsigned p) {
    asm volatile("{\n\t.reg .pred P;\n\tWL%=:\n\t"
        "mbarrier.try_wait.parity.acquire.cta.shared::cta.b64 P, [%0], %1, 0x989680;\n\t"
        "@P bra.uni WD%=;\n\tbra.uni WL%=;\n\tWD%=:\n\t}" :: "r"(a), "r"(p) : "memory");
}
__device__ __forceinline__ unsigned pack_bf16x2(float a, float b) {
    unsigned sa = __bfloat16_as_ushort(__float2bfloat16(a));
    unsigned sb = __bfloat16_as_ushort(__float2bfloat16(b));
    return sa | (sb << 16);
}
__device__ __forceinline__ void split2(float a, float b, unsigned& uh, unsigned& ul) {
    __nv_bfloat16 ha = __float2bfloat16(a), hb = __float2bfloat16(b);
    uh = (unsigned)__bfloat16_as_ushort(ha) | ((unsigned)__bfloat16_as_ushort(hb) << 16);
    ul = pack_bf16x2(a - __bfloat162float(ha), b - __bfloat162float(hb));
}
__device__ __forceinline__ float exp2_poly(float y) {
    float t = y + 12582912.0f;
    int k = __float_as_int(t);
    float f = y - (t - 12582912.0f);
    float p = 1.3333558146e-3f;
    p = fmaf(p, f, 9.6181291076e-3f);
    p = fmaf(p, f, 5.5504108664e-2f);
    p = fmaf(p, f, 2.4022650696e-1f);
    p = fmaf(p, f, 6.9314718056e-1f);
    p = fmaf(p, f, 1.0f);
    return __int_as_float(__float_as_int(p) + (k << 23));
}

// ---------------- small kernels ----------------
__global__ void bias_fill_kernel(const float* __restrict__ table, float* __restrict__ out_remain) {
    int idx = blockIdx.x * blockDim.x + threadIdx.x;
    if (idx < NH * 4096) {
        int h = idx >> 12;
        int rel = (idx & 4095) - 2047;
        int a = rel < 0 ? -rel : rel;
        int b;
        if (a < 8) b = a;
        else {
            int e = 28 - __clz(a);
            long long aa = (long long)a * (long long)a;
            b = 8 + 2*e + ((aa >= (1LL << (2*e + 7))) ? 1 : 0);
            if (b > 15) b = 15;
        }
        int bucket = (rel > 0 ? 16 : 0) + b;
        float val = table[bucket * NH + h];
        g_bias[idx] = val;
        g_bias2[idx] = val * LOG2E;
    }
    if (out_remain != nullptr && idx < 8) out_remain[idx] = (float)idx;
}

__global__ void pb_write_kernel(float* __restrict__ out_pb) {
    int q = blockIdx.x, h = blockIdx.y;
    const float* brow = g_bias + h * 4096 + (2047 - q);
    float* dst = out_pb + ((size_t)(h * SEQ + q)) * SEQ;
    int t = threadIdx.x;
    #pragma unroll
    for (int it = 0; it < 2; it++) {
        int k4 = (t + it * 256) * 4;
        *(float4*)&dst[k4] = make_float4(brow[k4], brow[k4+1], brow[k4+2], brow[k4+3]);
    }
}

__global__ void split_w_kernel(const float* __restrict__ wq, const float* __restrict__ wk,
                               const float* __restrict__ wv, const float* __restrict__ wo) {
    int idx = blockIdx.x * 256 + threadIdx.x;
    const float* src = (idx < WELEMS) ? wq : (idx < 2*WELEMS) ? wk : (idx < 3*WELEMS) ? wv : wo;
    float x = src[idx & (WELEMS - 1)];
    __nv_bfloat16 h = __float2bfloat16(x);
    g_whi[idx] = h;
    g_wlo[idx] = __float2bfloat16(x - __bfloat162float(h));
}

__global__ void split_a_kernel(const float* __restrict__ hidden, const float* __restrict__ lnw) {
    int m = blockIdx.x, t = threadIdx.x;
    float4 v = *(const float4*)&hidden[(size_t)m * DM + t * 4];
    float s = v.x*v.x + v.y*v.y + v.z*v.z + v.w*v.w;
    #pragma unroll
    for (int off = 16; off > 0; off >>= 1) s += __shfl_xor_sync(0xffffffffu, s, off);
    __shared__ float ws[4];
    if ((t & 31) == 0) ws[t >> 5] = s;
    __syncthreads();
    float rms = rsqrtf((ws[0]+ws[1]+ws[2]+ws[3]) * (1.0f/(float)DM) + 1e-6f);
    float4 l = *(const float4*)&lnw[t * 4];
    float a0 = v.x*l.x*rms, a1 = v.y*l.y*rms, a2 = v.z*l.z*rms, a3 = v.w*l.w*rms;
    unsigned uh0, ul0, uh1, ul1;
    split2(a0, a1, uh0, ul0);
    split2(a2, a3, uh1, ul1);
    *(uint2*)&g_ahi[(size_t)m * DM + t * 4] = make_uint2(uh0, uh1);
    *(uint2*)&g_alo[(size_t)m * DM + t * 4] = make_uint2(ul0, ul1);
}

// ---------------------------------------------------------------------------
// bf16x3 mma.sync GEMM, TMA-fed 2-stage pipeline (unchanged).
// ---------------------------------------------------------------------------
#define G_STG 49152u
#define G_DSM (2*49152 + 1024)

__global__ __launch_bounds__(256) void mma_gemm_kernel(
    const __grid_constant__ CUtensorMap mAh, const __grid_constant__ CUtensorMap mAl,
    const __grid_constant__ CUtensorMap mWh, const __grid_constant__ CUtensorMap mWl,
    int wbase, float* __restrict__ DstF,
    __nv_bfloat16* __restrict__ DstH, __nv_bfloat16* __restrict__ DstL,
    long long dzs, const float* __restrict__ resid, int qkv_mode)
{
    extern __shared__ char gsm[];
    __shared__ __align__(8) unsigned long long mb[2];
    unsigned sb = (smem_u32(gsm) + 1023u) & ~1023u;
    int t = threadIdx.x, w = t >> 5, lane = t & 31;
    int n0 = blockIdx.x * 64, m0 = blockIdx.y * 128, z = blockIdx.z;
    int wm = (w >> 1) * 32, wn = (w & 1) * 32;
    int wr = (wbase + z) * DM;

    float c[2][4][4];
    #pragma unroll
    for (int i = 0; i < 2; i++)
        #pragma unroll
        for (int j = 0; j < 4; j++)
            #pragma unroll
            for (int k = 0; k < 4; k++) c[i][j][k] = 0.0f;

    int lrowA = lane & 15, lkA = (lane >> 4) * 8;
    int lkB = (lane & 7) + ((lane & 8) ? 8 : 0);
    int lnB = (lane & 16) ? 8 : 0;

    if (t == 0) { MBAR_INIT(smem_u32(&mb[0]), 1); MBAR_INIT(smem_u32(&mb[1]), 1); }
    __syncthreads();
    if (t == 0) {
        unsigned m0b = smem_u32(&mb[0]);
        MBAR_EXPECT(m0b, G_STG);
        tma2(sb,         &mAh, 0, m0, m0b);
        tma2(sb + 16384, &mAl, 0, m0, m0b);
        tma2(sb + 32768, &mWh, n0, wr, m0b);
        tma2(sb + 40960, &mWl, n0, wr, m0b);
    }
    int ph[2] = {0, 0};
    for (int s = 0; s < 8; s++) {
        int b = s & 1;
        unsigned st = sb + (unsigned)b * G_STG;
        if (s + 1 < 8 && t == 0) {
            unsigned sn = sb + (unsigned)(b ^ 1) * G_STG;
            unsigned mbn = smem_u32(&mb[b ^ 1]);
            MBAR_EXPECT(mbn, G_STG);
            tma2(sn,         &mAh, (s+1)*64, m0, mbn);
            tma2(sn + 16384, &mAl, (s+1)*64, m0, mbn);
            tma2(sn + 32768, &mWh, n0, wr + (s+1)*64, mbn);
            tma2(sn + 40960, &mWl, n0, wr + (s+1)*64, mbn);
        }
        mbar_wait(smem_u32(&mb[b]), ph[b]); ph[b] ^= 1;

        #pragma unroll
        for (int kk = 0; kk < 64; kk += 16) {
            unsigned ah[2][4], al[2][4], bh[2][4], bl[2][4];
            #pragma unroll
            for (int mf = 0; mf < 2; mf++) {
                unsigned sa = sw128((unsigned)((wm + mf*16 + lrowA)*128 + (kk + lkA)*2));
                ldsm4(ah[mf], st + sa);
                ldsm4(al[mf], st + 16384 + sa);
            }
            #pragma unroll
            for (int nh = 0; nh < 2; nh++) {
                unsigned sa = sw128((unsigned)((kk + lkB)*128 + (wn + nh*16 + lnB)*2));
                ldsm4t(bh[nh], st + 32768 + sa);
                ldsm4t(bl[nh], st + 40960 + sa);
            }
            #pragma unroll
            for (int mf = 0; mf < 2; mf++)
                #pragma unroll
                for (int nf = 0; nf < 4; nf++) {
                    unsigned b0h = bh[nf >> 1][(nf & 1)*2], b1h = bh[nf >> 1][(nf & 1)*2 + 1];
                    unsigned b0l = bl[nf >> 1][(nf & 1)*2], b1l = bl[nf >> 1][(nf & 1)*2 + 1];
                    mma16816(c[mf][nf], ah[mf], b0h, b1h);
                    mma16816(c[mf][nf], ah[mf], b0l, b1l);
                    mma16816(c[mf][nf], al[mf], b0h, b1h);
                }
        }
        __syncthreads();
    }

    int g = lane >> 2, tc = (lane & 3) * 2;
    float sc = (qkv_mode && z == 0) ? LOG2E : 1.0f;
    #pragma unroll
    for (int mf = 0; mf < 2; mf++)
        #pragma unroll
        for (int nf = 0; nf < 4; nf++) {
            int row = m0 + wm + mf*16 + g;
            int col = n0 + wn + nf*8 + tc;
            float v0 = c[mf][nf][0]*sc, v1 = c[mf][nf][1]*sc;
            float v2 = c[mf][nf][2]*sc, v3 = c[mf][nf][3]*sc;
            if (DstF) {
                if (resid) {
                    float2 r0 = *(const float2*)&resid[(size_t)row*DM + col];
                    float2 r1 = *(const float2*)&resid[(size_t)(row+8)*DM + col];
                    v0 += r0.x; v1 += r0.y; v2 += r1.x; v3 += r1.y;
                }
                *(float2*)&DstF[(size_t)row*DM + col] = make_float2(v0, v1);
                *(float2*)&DstF[(size_t)(row+8)*DM + col] = make_float2(v2, v3);
            } else {
                size_t zo = (size_t)z * dzs;
                unsigned uh, ul;
                split2(v0, v1, uh, ul);
                *(unsigned*)&DstH[zo + (size_t)row*DM + col] = uh;
                *(unsigned*)&DstL[zo + (size_t)row*DM + col] = ul;
                split2(v2, v3, uh, ul);
                *(unsigned*)&DstH[zo + (size_t)(row+8)*DM + col] = uh;
                *(unsigned*)&DstL[zo + (size_t)(row+8)*DM + col] = ul;
            }
        }
}

// ---------------------------------------------------------------------------
// Flash attention, TMA-fed, exp2 interleaved with PV MMAs (unchanged).
// ---------------------------------------------------------------------------
#define ATT_STG 32768u
#define ATT_DSM (65536 + 1536 + 1024)

__global__ __launch_bounds__(256) void attn_mma_kernel(
    const __grid_constant__ CUtensorMap mH, const __grid_constant__ CUtensorMap mL,
    const __nv_bfloat16* __restrict__ Qh, const __nv_bfloat16* __restrict__ Ql,
    __nv_bfloat16* __restrict__ Chi, __nv_bfloat16* __restrict__ Clo,
    const float* __restrict__ Bias2)
{
    extern __shared__ char dyns[];
    __shared__ __align__(8) unsigned long long mb[2];
    unsigned sb = (smem_u32(dyns) + 1023u) & ~1023u;
    char* ab = dyns + (sb - smem_u32(dyns));
    float* sB = (float*)(ab + 65536);

    int t = threadIdx.x, w = t >> 5, lane = t & 31;
    int g = lane >> 2, cq = lane & 3;
    int q0 = blockIdx.x * 128, h = blockIdx.y, n = blockIdx.z;
    size_t base = ((size_t)n * SEQ) * DM + h * DKV;
    const float* brow = Bias2 + h * 4096;

    if (t == 0) { MBAR_INIT(smem_u32(&mb[0]), 1); MBAR_INIT(smem_u32(&mb[1]), 1); }

    {
        __nv_bfloat16* Qs_h = (__nv_bfloat16*)ab;
        __nv_bfloat16* Qs_l = (__nv_bfloat16*)(ab + 18432);
        #pragma unroll
        for (int it = 0; it < 4; it++) {
            int slot = t + 256*it;
            int row = slot >> 3, c8 = (slot & 7) * 8;
            *(uint4*)&Qs_h[row*72 + c8] = *(const uint4*)&Qh[base + (size_t)(q0+row)*DM + c8];
            *(uint4*)&Qs_l[row*72 + c8] = *(const uint4*)&Ql[base + (size_t)(q0+row)*DM + c8];
        }
    }
    __syncthreads();
    unsigned qfh[4][4], qfl[4][4];
    #pragma unroll
    for (int kk = 0; kk < 4; kk++) {
        unsigned addr = (unsigned)((16*w + (lane & 15))*72 + 16*kk + ((lane >> 4)*8)) * 2;
        ldsm4(qfh[kk], sb + addr);
        ldsm4(qfl[kk], sb + 18432 + addr);
    }
    __syncthreads();

    float O[8][4];
    #pragma unroll
    for (int j = 0; j < 8; j++)
        #pragma unroll
        for (int e = 0; e < 4; e++) O[j][e] = 0.0f;
    float lac0 = 0.0f, lac1 = 0.0f;

    int yK = ROWS + n*SEQ;
    if (t == 0) {
        unsigned m0b = smem_u32(&mb[0]);
        MBAR_EXPECT(m0b, ATT_STG);
        tma2(sb,         &mH, h*64, yK, m0b);
        tma2(sb + 8192,  &mL, h*64, yK, m0b);
        tma2(sb + 16384, &mH, h*64, yK + ROWS, m0b);
        tma2(sb + 24576, &mL, h*64, yK + ROWS, m0b);
    }
    if (t < 192) sB[t] = brow[0 - q0 + 1920 + t];
    __syncthreads();

    int ph[2] = {0, 0};
    const int NB = SEQ / 64;
    int r0 = 16*w + g;
    for (int kb = 0; kb < NB; kb++) {
        int st = kb & 1;
        unsigned stc = sb + (unsigned)st * ATT_STG;
        if (kb + 1 < NB) {
            if (t == 0) {
                unsigned stn = sb + (unsigned)(st ^ 1) * ATT_STG;
                unsigned mbn = smem_u32(&mb[st ^ 1]);
                MBAR_EXPECT(mbn, ATT_STG);
                int y = yK + (kb+1)*64;
                tma2(stn,         &mH, h*64, y, mbn);
                tma2(stn + 8192,  &mL, h*64, y, mbn);
                tma2(stn + 16384, &mH, h*64, y + ROWS, mbn);
                tma2(stn + 24576, &mL, h*64, y + ROWS, mbn);
            }
            if (t < 192) sB[(st^1)*192 + t] = brow[(kb+1)*64 - q0 + 1920 + t];
        }
        mbar_wait(smem_u32(&mb[st]), ph[st]); ph[st] ^= 1;
        const float* sBc = sB + st*192;

        float S[8][4];
        #pragma unroll
        for (int j = 0; j < 8; j++)
            #pragma unroll
            for (int e = 0; e < 4; e++) S[j][e] = 0.0f;

        #pragma unroll
        for (int kk = 0; kk < 4; kk++) {
            #pragma unroll
            for (int u = 0; u < 4; u++) {
                unsigned bh[4], bl[4];
                unsigned sa = sw128((unsigned)((16*u + (lane & 7) + ((lane & 16) ? 8 : 0))*128
                                               + 32*kk + ((lane & 8) ? 16 : 0)));
                ldsm4(bh, stc + sa);
                ldsm4(bl, stc + 8192 + sa);
                #pragma unroll
                for (int jj = 0; jj < 2; jj++) {
                    int j = 2*u + jj;
                    mma16816(S[j], qfh[kk], bh[2*jj], bh[2*jj+1]);
                    mma16816(S[j], qfl[kk], bh[2*jj], bh[2*jj+1]);
                    mma16816(S[j], qfh[kk], bl[2*jj], bl[2*jj+1]);
                }
            }
        }

        #pragma unroll
        for (int kkk = 0; kkk < 4; kkk++) {
            unsigned aPh4[4], aPl4[4];
            #pragma unroll
            for (int jj = 0; jj < 2; jj++) {
                int j = 2*kkk + jj;
                int col = 8*j + 2*cq;
                float p0 = exp2_poly(S[j][0] + sBc[col     - r0 + 127]);
                float p1 = exp2_poly(S[j][1] + sBc[col + 1 - r0 + 127]);
                float p2 = exp2_poly(S[j][2] + sBc[col     - r0 + 119]);
                float p3 = exp2_poly(S[j][3] + sBc[col + 1 - r0 + 119]);
                lac0 += p0 + p1;
                lac1 += p2 + p3;
                unsigned uh01, ul01, uh23, ul23;
                split2(p0, p1, uh01, ul01);
                split2(p2, p3, uh23, ul23);
                aPh4[jj*2    ] = uh01;
                aPh4[jj*2 + 1] = uh23;
                aPl4[jj*2    ] = ul01;
                aPl4[jj*2 + 1] = ul23;
            }
            #pragma unroll
            for (int u2 = 0; u2 < 4; u2++) {
                unsigned bh[4], bl[4];
                unsigned sa = sw128((unsigned)((16*kkk + (lane & 7) + ((lane & 8) ? 8 : 0))*128
                                               + 32*u2 + ((lane & 16) ? 16 : 0)));
                ldsm4t(bh, stc + 16384 + sa);
                ldsm4t(bl, stc + 24576 + sa);
                #pragma unroll
                for (int jj = 0; jj < 2; jj++) {
                    int j = 2*u2 + jj;
                    mma16816(O[j], aPh4, bh[2*jj], bh[2*jj+1]);
                    mma16816(O[j], aPl4, bh[2*jj], bh[2*jj+1]);
                    mma16816(O[j], aPh4, bl[2*jj], bl[2*jj+1]);
                }
            }
        }
        __syncthreads();
    }

    lac0 += __shfl_xor_sync(0xffffffffu, lac0, 1);
    lac0 += __shfl_xor_sync(0xffffffffu, lac0, 2);
    lac1 += __shfl_xor_sync(0xffffffffu, lac1, 1);
    lac1 += __shfl_xor_sync(0xffffffffu, lac1, 2);
    float li0 = 1.0f / lac0, li1 = 1.0f / lac1;

    size_t rowA = base + (size_t)(q0 + 16*w + g) * DM;
    size_t rowB = base + (size_t)(q0 + 16*w + g + 8) * DM;
    #pragma unroll
    for (int j = 0; j < 8; j++) {
        int col = 8*j + 2*cq;
        unsigned uh, ul;
        split2(O[j][0] * li0, O[j][1] * li0, uh, ul);
        *(unsigned*)&Chi[rowA + col] = uh;
        *(unsigned*)&Clo[rowA + col] = ul;
        split2(O[j][2] * li1, O[j][3] * li1, uh, ul);
        *(unsigned*)&Chi[rowB + col] = uh;
        *(unsigned*)&Clo[rowB + col] = ul;
    }
}

// ---------------------------------------------------------------------------
typedef CUresult (*EncodeFn)(CUtensorMap*, CUtensorMapDataType, cuuint32_t, void*,
    const cuuint64_t*, const cuuint64_t*, const cuuint32_t*, const cuuint32_t*,
    CUtensorMapInterleave, CUtensorMapSwizzle, CUtensorMapL2promotion, CUtensorMapFloatOOBfill);

static void mk_map(CUtensorMap* m, void* p, unsigned long long inner, unsigned long long outer,
                   unsigned bx, unsigned by) {
    static EncodeFn fn = nullptr;
    if (!fn) {
        cudaDriverEntryPointQueryResult qr;
        cudaGetDriverEntryPointByVersion("cuTensorMapEncodeTiled", (void**)&fn, 12000,
                                         cudaEnableDefault, &qr);
    }
    cuuint64_t d[2] = {inner, outer}, s[1] = {inner * 2};
    cuuint32_t b[2] = {bx, by}, e[2] = {1, 1};
    fn(m, CU_TENSOR_MAP_DATA_TYPE_BFLOAT16, 2, p, d, s, b, e,
       CU_TENSOR_MAP_INTERLEAVE_NONE, CU_TENSOR_MAP_SWIZZLE_128B,
       CU_TENSOR_MAP_L2_PROMOTION_L2_128B, CU_TENSOR_MAP_FLOAT_OOB_FILL_NONE);
}

extern "C" void kernel_launch(void* const* d_in, const int* in_sizes, int n_in,
                              void* d_out, int out_size) {
    const float* hidden = (const float*)d_in[0];
    const float* lnw    = (const float*)d_in[1];
    const float* wq     = (const float*)d_in[2];
    const float* wk     = (const float*)d_in[3];
    const float* wv     = (const float*)d_in[4];
    const float* wo     = (const float*)d_in[5];
    const float* table  = (const float*)d_in[6];
    float* out = (float*)d_out;

    float *pbias2;
    __nv_bfloat16 *pahi, *palo, *pwhi, *pwlo, *pqh, *pql;
    cudaGetSymbolAddress((void**)&pbias2, g_bias2);
    cudaGetSymbolAddress((void**)&pahi,   g_ahi);
    cudaGetSymbolAddress((void**)&palo,   g_alo);
    cudaGetSymbolAddress((void**)&pwhi,   g_whi);
    cudaGetSymbolAddress((void**)&pwlo,   g_wlo);
    cudaGetSymbolAddress((void**)&pqh,    g_qkvh);
    cudaGetSymbolAddress((void**)&pql,    g_qkvl);

    CUtensorMap mAh, mAl, mWh, mWl, mQh, mQl;
    mk_map(&mAh, pahi, DM, ROWS,   64, 128);
    mk_map(&mAl, palo, DM, ROWS,   64, 128);
    mk_map(&mWh, pwhi, DM, 4*DM,   64, 64);
    mk_map(&mWl, pwlo, DM, 4*DM,   64, 64);
    mk_map(&mQh, pqh,  DM, 3*ROWS, 64, 64);
    mk_map(&mQl, pql,  DM, 3*ROWS, 64, 64);

    cudaFuncSetAttribute(attn_mma_kernel, cudaFuncAttributeMaxDynamicSharedMemorySize, ATT_DSM);
    cudaFuncSetAttribute(mma_gemm_kernel, cudaFuncAttributeMaxDynamicSharedMemorySize, G_DSM);

    // side stream + events for overlapping the pb/bias path with the GEMM path
    static cudaStream_t s2 = nullptr;
    static cudaEvent_t ev_fork = nullptr, ev_join = nullptr;
    if (s2 == nullptr) {
        cudaStreamCreateWithFlags(&s2, cudaStreamNonBlocking);
        cudaEventCreateWithFlags(&ev_fork, cudaEventDisableTiming);
        cudaEventCreateWithFlags(&ev_join, cudaEventDisableTiming);
    }

    bool full = out_size >= (HID_ELEMS + PB_ELEMS + 8);
    float* out_pb     = out + HID_ELEMS;
    float* out_remain = out + HID_ELEMS + PB_ELEMS;

    // fork: side stream runs bias LUT + position-bias output (independent of
    // the split/GEMM chain); joined before attention (needs g_bias2).
    cudaEventRecord(ev_fork, 0);
    cudaStreamWaitEvent(s2, ev_fork, 0);
    bias_fill_kernel<<<128, 256, 0, s2>>>(table, full ? out_remain : nullptr);
    if (full) pb_write_kernel<<<dim3(SEQ, NH), 256, 0, s2>>>(out_pb);
    cudaEventRecord(ev_join, s2);

    split_w_kernel<<<4*WELEMS/256, 256>>>(wq, wk, wv, wo);
    split_a_kernel<<<ROWS, 128>>>(hidden, lnw);

    mma_gemm_kernel<<<dim3(DM/64, ROWS/128, 3), 256, G_DSM>>>(
        mAh, mAl, mWh, mWl, 0, nullptr, pqh, pql, (long long)HID_ELEMS, nullptr, 1);

    cudaStreamWaitEvent(0, ev_join, 0);   // bias2 ready for attention

    attn_mma_kernel<<<dim3(SEQ/128, NH, NBATCH), 256, ATT_DSM>>>(
        mQh, mQl, pqh, pql, pahi, palo, pbias2);

    mma_gemm_kernel<<<dim3(DM/64, ROWS/128, 1), 256, G_DSM>>>(
        mAh, mAl, mWh, mWl, 3, out, nullptr, nullptr, 0, hidden, 0);
}

// round 16
// speedup vs baseline: 1.1978x; 1.1978x over previous
#include <cuda_runtime.h>
#include <cuda.h>
#include <cuda_fp16.h>

#define NBATCH 8
#define SEQ 2048
#define DM 512
#define NH 8
#define DKV 64
#define ROWS (NBATCH*SEQ)
#define HID_ELEMS (ROWS*DM)
#define PB_ELEMS (NH*SEQ*SEQ)
#define WELEMS (DM*DM)
#define LOG2E 1.4426950408889634f

__device__ float g_bias[NH*4096];
__device__ float g_bias2[NH*4096];
__device__ __half g_ahi[HID_ELEMS];
__device__ __half g_alo[HID_ELEMS];
__device__ __half g_whi[4*WELEMS];    // [z][k][n]
__device__ __half g_wlo[4*WELEMS];
__device__ __half g_qkvh[3*HID_ELEMS];
__device__ __half g_qkvl[3*HID_ELEMS];

// ---------------- helpers ----------------
__device__ __forceinline__ unsigned smem_u32(const void* p) {
    unsigned a;
    asm("{ .reg .u64 t; cvta.to.shared.u64 t, %1; cvt.u32.u64 %0, t; }" : "=r"(a) : "l"(p));
    return a;
}
__device__ __forceinline__ unsigned sw128(unsigned x) { return x ^ ((x >> 3) & 0x70u); }
__device__ __forceinline__ void ldsm4(unsigned* r, unsigned addr) {
    asm volatile("ldmatrix.sync.aligned.m8n8.x4.shared.b16 {%0,%1,%2,%3}, [%4];"
        : "=r"(r[0]), "=r"(r[1]), "=r"(r[2]), "=r"(r[3]) : "r"(addr));
}
__device__ __forceinline__ void ldsm4t(unsigned* r, unsigned addr) {
    asm volatile("ldmatrix.sync.aligned.m8n8.x4.trans.shared.b16 {%0,%1,%2,%3}, [%4];"
        : "=r"(r[0]), "=r"(r[1]), "=r"(r[2]), "=r"(r[3]) : "r"(addr));
}
__device__ __forceinline__ void mma16816(float* c, const unsigned* a, unsigned b0, unsigned b1) {
    asm volatile("mma.sync.aligned.m16n8k16.row.col.f32.f16.f16.f32 "
        "{%0,%1,%2,%3}, {%4,%5,%6,%7}, {%8,%9}, {%0,%1,%2,%3};"
        : "+f"(c[0]), "+f"(c[1]), "+f"(c[2]), "+f"(c[3])
        : "r"(a[0]), "r"(a[1]), "r"(a[2]), "r"(a[3]), "r"(b0), "r"(b1));
}
__device__ __forceinline__ void tma2(unsigned dst, const CUtensorMap* m, int x, int y, unsigned mbar) {
    asm volatile("cp.async.bulk.tensor.2d.shared::cta.global.tile.mbarrier::complete_tx::bytes "
        "[%0], [%1, {%2, %3}], [%4];" :: "r"(dst), "l"(m), "r"(x), "r"(y), "r"(mbar) : "memory");
}
#define MBAR_INIT(a,c)   asm volatile("mbarrier.init.shared.b64 [%0], %1;" :: "r"((unsigned)(a)), "r"((unsigned)(c)) : "memory")
#define MBAR_EXPECT(a,b) asm volatile("mbarrier.arrive.expect_tx.shared.b64 _, [%0], %1;" :: "r"((unsigned)(a)), "r"((unsigned)(b)) : "memory")
__device__ __forceinline__ void mbar_wait(unsigned a, unsigned p) {
    asm volatile("{\n\t.reg .pred P;\n\tWL%=:\n\t"
        "mbarrier.try_wait.parity.acquire.cta.shared::cta.b64 P, [%0], %1, 0x989680;\n\t"
        "@P bra.uni WD%=;\n\tbra.uni WL%=;\n\tWD%=:\n\t}" :: "r"(a), "r"(p) : "memory");
}
__device__ __forceinline__ unsigned pack_f16x2(float a, float b) {
    __half2 h = __floats2half2_rn(a, b);
    return *(unsigned*)&h;
}
__device__ __forceinline__ void split2(float a, float b, unsigned& uh, unsigned& ul) {
    __half ha = __float2half_rn(a), hb = __float2half_rn(b);
    unsigned sa = __half_as_ushort(ha), sb_ = __half_as_ushort(hb);
    uh = sa | (sb_ << 16);
    ul = pack_f16x2(a - __half2float(ha), b - __half2float(hb));
}
// exp2 on FMA pipe; arg clamped to [-126, +] so the magic-constant trick and
// the exponent add never go out of range (fp16-safe P needs y <= 0 anyway).
__device__ __forceinline__ float exp2_poly(float y) {
    y = fmaxf(y, -126.0f);
    float t = y + 12582912.0f;
    int k = __float_as_int(t);
    float f = y - (t - 12582912.0f);
    float p = 1.3333558146e-3f;
    p = fmaf(p, f, 9.6181291076e-3f);
    p = fmaf(p, f, 5.5504108664e-2f);
    p = fmaf(p, f, 2.4022650696e-1f);
    p = fmaf(p, f, 6.9314718056e-1f);
    p = fmaf(p, f, 1.0f);
    return __int_as_float(__float_as_int(p) + (k << 23));
}

// ---------------- small kernels ----------------
__global__ void bias_fill_kernel(const float* __restrict__ table, float* __restrict__ out_remain) {
    int idx = blockIdx.x * blockDim.x + threadIdx.x;
    if (idx < NH * 4096) {
        int h = idx >> 12;
        int rel = (idx & 4095) - 2047;
        int a = rel < 0 ? -rel : rel;
        int b;
        if (a < 8) b = a;
        else {
            int e = 28 - __clz(a);
            long long aa = (long long)a * (long long)a;
            b = 8 + 2*e + ((aa >= (1LL << (2*e + 7))) ? 1 : 0);
            if (b > 15) b = 15;
        }
        int bucket = (rel > 0 ? 16 : 0) + b;
        float val = table[bucket * NH + h];
        g_bias[idx] = val;
        g_bias2[idx] = val * LOG2E;
    }
    if (out_remain != nullptr && idx < 8) out_remain[idx] = (float)idx;
}

__global__ void pb_write_kernel(float* __restrict__ out_pb) {
    int q = blockIdx.x, h = blockIdx.y;
    const float* brow = g_bias + h * 4096 + (2047 - q);
    float* dst = out_pb + ((size_t)(h * SEQ + q)) * SEQ;
    int t = threadIdx.x;
    #pragma unroll
    for (int it = 0; it < 2; it++) {
        int k4 = (t + it * 256) * 4;
        *(float4*)&dst[k4] = make_float4(brow[k4], brow[k4+1], brow[k4+2], brow[k4+3]);
    }
}

__global__ void split_w_kernel(const float* __restrict__ wq, const float* __restrict__ wk,
                               const float* __restrict__ wv, const float* __restrict__ wo) {
    int idx = blockIdx.x * 256 + threadIdx.x;
    const float* src = (idx < WELEMS) ? wq : (idx < 2*WELEMS) ? wk : (idx < 3*WELEMS) ? wv : wo;
    float x = src[idx & (WELEMS - 1)];
    __half h = __float2half_rn(x);
    g_whi[idx] = h;
    g_wlo[idx] = __float2half_rn(x - __half2float(h));
}

__global__ void split_a_kernel(const float* __restrict__ hidden, const float* __restrict__ lnw) {
    int m = blockIdx.x, t = threadIdx.x;
    float4 v = *(const float4*)&hidden[(size_t)m * DM + t * 4];
    float s = v.x*v.x + v.y*v.y + v.z*v.z + v.w*v.w;
    #pragma unroll
    for (int off = 16; off > 0; off >>= 1) s += __shfl_xor_sync(0xffffffffu, s, off);
    __shared__ float ws[4];
    if ((t & 31) == 0) ws[t >> 5] = s;
    __syncthreads();
    float rms = rsqrtf((ws[0]+ws[1]+ws[2]+ws[3]) * (1.0f/(float)DM) + 1e-6f);
    float4 l = *(const float4*)&lnw[t * 4];
    float a0 = v.x*l.x*rms, a1 = v.y*l.y*rms, a2 = v.z*l.z*rms, a3 = v.w*l.w*rms;
    unsigned uh0, ul0, uh1, ul1;
    split2(a0, a1, uh0, ul0);
    split2(a2, a3, uh1, ul1);
    *(uint2*)&g_ahi[(size_t)m * DM + t * 4] = make_uint2(uh0, uh1);
    *(uint2*)&g_alo[(size_t)m * DM + t * 4] = make_uint2(ul0, ul1);
}

// ---------------------------------------------------------------------------
// fp16 error-split mma.sync GEMM, TMA-fed 2-stage pipeline.
// prod3_mask bit z: 1 -> 3 products, 0 -> 2 products (A full x W-hi).
// ---------------------------------------------------------------------------
#define G_STG 49152u
#define G_DSM (2*49152 + 1024)

__global__ __launch_bounds__(256) void mma_gemm_kernel(
    const __grid_constant__ CUtensorMap mAh, const __grid_constant__ CUtensorMap mAl,
    const __grid_constant__ CUtensorMap mWh, const __grid_constant__ CUtensorMap mWl,
    int wbase, int prod3_mask, float* __restrict__ DstF,
    __half* __restrict__ DstH, __half* __restrict__ DstL,
    long long dzs, const float* __restrict__ resid, int qkv_mode)
{
    extern __shared__ char gsm[];
    __shared__ __align__(8) unsigned long long mb[2];
    unsigned sb = (smem_u32(gsm) + 1023u) & ~1023u;
    int t = threadIdx.x, w = t >> 5, lane = t & 31;
    int n0 = blockIdx.x * 64, m0 = blockIdx.y * 128, z = blockIdx.z;
    int wm = (w >> 1) * 32, wn = (w & 1) * 32;
    int wr = (wbase + z) * DM;
    bool p3 = (prod3_mask >> z) & 1;

    float c[2][4][4];
    #pragma unroll
    for (int i = 0; i < 2; i++)
        #pragma unroll
        for (int j = 0; j < 4; j++)
            #pragma unroll
            for (int k = 0; k < 4; k++) c[i][j][k] = 0.0f;

    int lrowA = lane & 15, lkA = (lane >> 4) * 8;
    int lkB = (lane & 7) + ((lane & 8) ? 8 : 0);
    int lnB = (lane & 16) ? 8 : 0;

    if (t == 0) { MBAR_INIT(smem_u32(&mb[0]), 1); MBAR_INIT(smem_u32(&mb[1]), 1); }
    __syncthreads();
    if (t == 0) {
        unsigned m0b = smem_u32(&mb[0]);
        MBAR_EXPECT(m0b, G_STG);
        tma2(sb,         &mAh, 0, m0, m0b);
        tma2(sb + 16384, &mAl, 0, m0, m0b);
        tma2(sb + 32768, &mWh, n0, wr, m0b);
        tma2(sb + 40960, &mWl, n0, wr, m0b);
    }
    int ph[2] = {0, 0};
    for (int s = 0; s < 8; s++) {
        int b = s & 1;
        unsigned st = sb + (unsigned)b * G_STG;
        if (s + 1 < 8 && t == 0) {
            unsigned sn = sb + (unsigned)(b ^ 1) * G_STG;
            unsigned mbn = smem_u32(&mb[b ^ 1]);
            MBAR_EXPECT(mbn, G_STG);
            tma2(sn,         &mAh, (s+1)*64, m0, mbn);
            tma2(sn + 16384, &mAl, (s+1)*64, m0, mbn);
            tma2(sn + 32768, &mWh, n0, wr + (s+1)*64, mbn);
            tma2(sn + 40960, &mWl, n0, wr + (s+1)*64, mbn);
        }
        mbar_wait(smem_u32(&mb[b]), ph[b]); ph[b] ^= 1;

        #pragma unroll
        for (int kk = 0; kk < 64; kk += 16) {
            unsigned ah[2][4], al[2][4], bh[2][4], bl[2][4];
            #pragma unroll
            for (int mf = 0; mf < 2; mf++) {
                unsigned sa = sw128((unsigned)((wm + mf*16 + lrowA)*128 + (kk + lkA)*2));
                ldsm4(ah[mf], st + sa);
                ldsm4(al[mf], st + 16384 + sa);
            }
            #pragma unroll
            for (int nh = 0; nh < 2; nh++) {
                unsigned sa = sw128((unsigned)((kk + lkB)*128 + (wn + nh*16 + lnB)*2));
                ldsm4t(bh[nh], st + 32768 + sa);
                if (p3) ldsm4t(bl[nh], st + 40960 + sa);
            }
            #pragma unroll
            for (int mf = 0; mf < 2; mf++)
                #pragma unroll
                for (int nf = 0; nf < 4; nf++) {
                    unsigned b0h = bh[nf >> 1][(nf & 1)*2], b1h = bh[nf >> 1][(nf & 1)*2 + 1];
                    mma16816(c[mf][nf], ah[mf], b0h, b1h);
                    mma16816(c[mf][nf], al[mf], b0h, b1h);
                    if (p3) {
                        unsigned b0l = bl[nf >> 1][(nf & 1)*2], b1l = bl[nf >> 1][(nf & 1)*2 + 1];
                        mma16816(c[mf][nf], ah[mf], b0l, b1l);
                    }
                }
        }
        __syncthreads();
    }

    int g = lane >> 2, tc = (lane & 3) * 2;
    float sc = (qkv_mode && z == 0) ? LOG2E : 1.0f;
    #pragma unroll
    for (int mf = 0; mf < 2; mf++)
        #pragma unroll
        for (int nf = 0; nf < 4; nf++) {
            int row = m0 + wm + mf*16 + g;
            int col = n0 + wn + nf*8 + tc;
            float v0 = c[mf][nf][0]*sc, v1 = c[mf][nf][1]*sc;
            float v2 = c[mf][nf][2]*sc, v3 = c[mf][nf][3]*sc;
            if (DstF) {
                if (resid) {
                    float2 r0 = *(const float2*)&resid[(size_t)row*DM + col];
                    float2 r1 = *(const float2*)&resid[(size_t)(row+8)*DM + col];
                    v0 += r0.x; v1 += r0.y; v2 += r1.x; v3 += r1.y;
                }
                *(float2*)&DstF[(size_t)row*DM + col] = make_float2(v0, v1);
                *(float2*)&DstF[(size_t)(row+8)*DM + col] = make_float2(v2, v3);
            } else {
                size_t zo = (size_t)z * dzs;
                unsigned uh, ul;
                split2(v0, v1, uh, ul);
                *(unsigned*)&DstH[zo + (size_t)row*DM + col] = uh;
                *(unsigned*)&DstL[zo + (size_t)row*DM + col] = ul;
                split2(v2, v3, uh, ul);
                *(unsigned*)&DstH[zo + (size_t)(row+8)*DM + col] = uh;
                *(unsigned*)&DstL[zo + (size_t)(row+8)*DM + col] = ul;
            }
        }
}

// ---------------------------------------------------------------------------
// Flash attention, TMA-fed, fp16 with ONLINE MAX (log2 domain) so P in (0,1]
// is fp16-safe. S = QK^T 3-product; PV single product. Stage = 24KB.
// ---------------------------------------------------------------------------
#define ATT_STG 24576u
#define ATT_DSM (49152 + 1536 + 1024)

__global__ __launch_bounds__(256) void attn_mma_kernel(
    const __grid_constant__ CUtensorMap mH, const __grid_constant__ CUtensorMap mL,
    const __half* __restrict__ Qh, const __half* __restrict__ Ql,
    __half* __restrict__ Chi, __half* __restrict__ Clo,
    const float* __restrict__ Bias2)
{
    extern __shared__ char dyns[];
    __shared__ __align__(8) unsigned long long mb[2];
    unsigned sb = (smem_u32(dyns) + 1023u) & ~1023u;
    char* ab = dyns + (sb - smem_u32(dyns));
    float* sB = (float*)(ab + 49152);

    int t = threadIdx.x, w = t >> 5, lane = t & 31;
    int g = lane >> 2, cq = lane & 3;
    int q0 = blockIdx.x * 128, h = blockIdx.y, n = blockIdx.z;
    size_t base = ((size_t)n * SEQ) * DM + h * DKV;
    const float* brow = Bias2 + h * 4096;

    if (t == 0) { MBAR_INIT(smem_u32(&mb[0]), 1); MBAR_INIT(smem_u32(&mb[1]), 1); }

    {   // Q prologue into stage area (consumed before first prefetch)
        __half* Qs_h = (__half*)ab;
        __half* Qs_l = (__half*)(ab + 18432);
        #pragma unroll
        for (int it = 0; it < 4; it++) {
            int slot = t + 256*it;
            int row = slot >> 3, c8 = (slot & 7) * 8;
            *(uint4*)&Qs_h[row*72 + c8] = *(const uint4*)&Qh[base + (size_t)(q0+row)*DM + c8];
            *(uint4*)&Qs_l[row*72 + c8] = *(const uint4*)&Ql[base + (size_t)(q0+row)*DM + c8];
        }
    }
    __syncthreads();
    unsigned qfh[4][4], qfl[4][4];
    #pragma unroll
    for (int kk = 0; kk < 4; kk++) {
        unsigned addr = (unsigned)((16*w + (lane & 15))*72 + 16*kk + ((lane >> 4)*8)) * 2;
        ldsm4(qfh[kk], sb + addr);
        ldsm4(qfl[kk], sb + 18432 + addr);
    }
    __syncthreads();

    float O[8][4];
    #pragma unroll
    for (int j = 0; j < 8; j++)
        #pragma unroll
        for (int e = 0; e < 4; e++) O[j][e] = 0.0f;
    float lac0 = 0.0f, lac1 = 0.0f;
    float mr0 = -1e30f, mr1 = -1e30f;   // running row max (log2 domain)

    int yK = ROWS + n*SEQ;
    if (t == 0) {
        unsigned m0b = smem_u32(&mb[0]);
        MBAR_EXPECT(m0b, ATT_STG);
        tma2(sb,         &mH, h*64, yK, m0b);
        tma2(sb + 8192,  &mL, h*64, yK, m0b);
        tma2(sb + 16384, &mH, h*64, yK + ROWS, m0b);
    }
    if (t < 192) sB[t] = brow[0 - q0 + 1920 + t];
    __syncthreads();

    int ph[2] = {0, 0};
    const int NB = SEQ / 64;
    int r0 = 16*w + g;
    for (int kb = 0; kb < NB; kb++) {
        int st = kb & 1;
        unsigned stc = sb + (unsigned)st * ATT_STG;
        if (kb + 1 < NB) {
            if (t == 0) {
                unsigned stn = sb + (unsigned)(st ^ 1) * ATT_STG;
                unsigned mbn = smem_u32(&mb[st ^ 1]);
                MBAR_EXPECT(mbn, ATT_STG);
                int y = yK + (kb+1)*64;
                tma2(stn,         &mH, h*64, y, mbn);
                tma2(stn + 8192,  &mL, h*64, y, mbn);
                tma2(stn + 16384, &mH, h*64, y + ROWS, mbn);
            }
            if (t < 192) sB[(st^1)*192 + t] = brow[(kb+1)*64 - q0 + 1920 + t];
        }
        mbar_wait(smem_u32(&mb[st]), ph[st]); ph[st] ^= 1;
        const float* sBc = sB + st*192;

        // ---- S = Q K^T (fp16 3-product) ----
        float S[8][4];
        #pragma unroll
        for (int j = 0; j < 8; j++)
            #pragma unroll
            for (int e = 0; e < 4; e++) S[j][e] = 0.0f;

        #pragma unroll
        for (int kk = 0; kk < 4; kk++) {
            #pragma unroll
            for (int u = 0; u < 4; u++) {
                unsigned bh[4], bl[4];
                unsigned sa = sw128((unsigned)((16*u + (lane & 7) + ((lane & 16) ? 8 : 0))*128
                                               + 32*kk + ((lane & 8) ? 16 : 0)));
                ldsm4(bh, stc + sa);
                ldsm4(bl, stc + 8192 + sa);
                #pragma unroll
                for (int jj = 0; jj < 2; jj++) {
                    int j = 2*u + jj;
                    mma16816(S[j], qfh[kk], bh[2*jj], bh[2*jj+1]);
                    mma16816(S[j], qfl[kk], bh[2*jj], bh[2*jj+1]);
                    mma16816(S[j], qfh[kk], bl[2*jj], bl[2*jj+1]);
                }
            }
        }

        // ---- bias + block-row max + online rescale (log2 domain) ----
        float bm0 = -1e30f, bm1 = -1e30f;
        #pragma unroll
        for (int j = 0; j < 8; j++) {
            int col = 8*j + 2*cq;
            S[j][0] += sBc[col     - r0 + 127];
            S[j][1] += sBc[col + 1 - r0 + 127];
            S[j][2] += sBc[col     - r0 + 119];
            S[j][3] += sBc[col + 1 - r0 + 119];
            bm0 = fmaxf(bm0, fmaxf(S[j][0], S[j][1]));
            bm1 = fmaxf(bm1, fmaxf(S[j][2], S[j][3]));
        }
        bm0 = fmaxf(bm0, __shfl_xor_sync(0xffffffffu, bm0, 1));
        bm0 = fmaxf(bm0, __shfl_xor_sync(0xffffffffu, bm0, 2));
        bm1 = fmaxf(bm1, __shfl_xor_sync(0xffffffffu, bm1, 1));
        bm1 = fmaxf(bm1, __shfl_xor_sync(0xffffffffu, bm1, 2));
        float nm0 = fmaxf(mr0, bm0), nm1 = fmaxf(mr1, bm1);
        float al0 = exp2_poly(mr0 - nm0), al1 = exp2_poly(mr1 - nm1);
        mr0 = nm0; mr1 = nm1;
        lac0 *= al0; lac1 *= al1;
        #pragma unroll
        for (int j = 0; j < 8; j++) {
            O[j][0] *= al0; O[j][1] *= al0;
            O[j][2] *= al1; O[j][3] *= al1;
        }

        // ---- interleaved: exp2+pack then single-product PV (P in (0,1]) ----
        #pragma unroll
        for (int kkk = 0; kkk < 4; kkk++) {
            unsigned aP4[4];
            #pragma unroll
            for (int jj = 0; jj < 2; jj++) {
                int j = 2*kkk + jj;
                float p0 = exp2_poly(S[j][0] - mr0);
                float p1 = exp2_poly(S[j][1] - mr0);
                float p2 = exp2_poly(S[j][2] - mr1);
                float p3 = exp2_poly(S[j][3] - mr1);
                lac0 += p0 + p1;
                lac1 += p2 + p3;
                aP4[jj*2    ] = pack_f16x2(p0, p1);
                aP4[jj*2 + 1] = pack_f16x2(p2, p3);
            }
            #pragma unroll
            for (int u2 = 0; u2 < 4; u2++) {
                unsigned bh[4];
                unsigned sa = sw128((unsigned)((16*kkk + (lane & 7) + ((lane & 8) ? 8 : 0))*128
                                               + 32*u2 + ((lane & 16) ? 16 : 0)));
                ldsm4t(bh, stc + 16384 + sa);
                #pragma unroll
                for (int jj = 0; jj < 2; jj++) {
                    int j = 2*u2 + jj;
                    mma16816(O[j], aP4, bh[2*jj], bh[2*jj+1]);
                }
            }
        }
        __syncthreads();
    }

    lac0 += __shfl_xor_sync(0xffffffffu, lac0, 1);
    lac0 += __shfl_xor_sync(0xffffffffu, lac0, 2);
    lac1 += __shfl_xor_sync(0xffffffffu, lac1, 1);
    lac1 += __shfl_xor_sync(0xffffffffu, lac1, 2);
    float li0 = 1.0f / lac0, li1 = 1.0f / lac1;

    size_t rowA = base + (size_t)(q0 + 16*w + g) * DM;
    size_t rowB = base + (size_t)(q0 + 16*w + g + 8) * DM;
    #pragma unroll
    for (int j = 0; j < 8; j++) {
        int col = 8*j + 2*cq;
        unsigned uh, ul;
        split2(O[j][0] * li0, O[j][1] * li0, uh, ul);
        *(unsigned*)&Chi[rowA + col] = uh;
        *(unsigned*)&Clo[rowA + col] = ul;
        split2(O[j][2] * li1, O[j][3] * li1, uh, ul);
        *(unsigned*)&Chi[rowB + col] = uh;
        *(unsigned*)&Clo[rowB + col] = ul;
    }
}

// ---------------------------------------------------------------------------
typedef CUresult (*EncodeFn)(CUtensorMap*, CUtensorMapDataType, cuuint32_t, void*,
    const cuuint64_t*, const cuuint64_t*, const cuuint32_t*, const cuuint32_t*,
    CUtensorMapInterleave, CUtensorMapSwizzle, CUtensorMapL2promotion, CUtensorMapFloatOOBfill);

static void mk_map(CUtensorMap* m, void* p, unsigned long long inner, unsigned long long outer,
                   unsigned bx, unsigned by) {
    static EncodeFn fn = nullptr;
    if (!fn) {
        cudaDriverEntryPointQueryResult qr;
        cudaGetDriverEntryPointByVersion("cuTensorMapEncodeTiled", (void**)&fn, 12000,
                                         cudaEnableDefault, &qr);
    }
    cuuint64_t d[2] = {inner, outer}, s[1] = {inner * 2};
    cuuint32_t b[2] = {bx, by}, e[2] = {1, 1};
    fn(m, CU_TENSOR_MAP_DATA_TYPE_FLOAT16, 2, p, d, s, b, e,
       CU_TENSOR_MAP_INTERLEAVE_NONE, CU_TENSOR_MAP_SWIZZLE_128B,
       CU_TENSOR_MAP_L2_PROMOTION_L2_128B, CU_TENSOR_MAP_FLOAT_OOB_FILL_NONE);
}

extern "C" void kernel_launch(void* const* d_in, const int* in_sizes, int n_in,
                              void* d_out, int out_size) {
    const float* hidden = (const float*)d_in[0];
    const float* lnw    = (const float*)d_in[1];
    const float* wq     = (const float*)d_in[2];
    const float* wk     = (const float*)d_in[3];
    const float* wv     = (const float*)d_in[4];
    const float* wo     = (const float*)d_in[5];
    const float* table  = (const float*)d_in[6];
    float* out = (float*)d_out;

    float *pbias2;
    __half *pahi, *palo, *pwhi, *pwlo, *pqh, *pql;
    cudaGetSymbolAddress((void**)&pbias2, g_bias2);
    cudaGetSymbolAddress((void**)&pahi,   g_ahi);
    cudaGetSymbolAddress((void**)&palo,   g_alo);
    cudaGetSymbolAddress((void**)&pwhi,   g_whi);
    cudaGetSymbolAddress((void**)&pwlo,   g_wlo);
    cudaGetSymbolAddress((void**)&pqh,    g_qkvh);
    cudaGetSymbolAddress((void**)&pql,    g_qkvl);

    CUtensorMap mAh, mAl, mWh, mWl, mQh, mQl;
    mk_map(&mAh, pahi, DM, ROWS,   64, 128);
    mk_map(&mAl, palo, DM, ROWS,   64, 128);
    mk_map(&mWh, pwhi, DM, 4*DM,   64, 64);
    mk_map(&mWl, pwlo, DM, 4*DM,   64, 64);
    mk_map(&mQh, pqh,  DM, 3*ROWS, 64, 64);
    mk_map(&mQl, pql,  DM, 3*ROWS, 64, 64);

    cudaFuncSetAttribute(attn_mma_kernel, cudaFuncAttributeMaxDynamicSharedMemorySize, ATT_DSM);
    cudaFuncSetAttribute(mma_gemm_kernel, cudaFuncAttributeMaxDynamicSharedMemorySize, G_DSM);

    static cudaStream_t s2 = nullptr;
    static cudaEvent_t ev_fork = nullptr, ev_join = nullptr;
    if (s2 == nullptr) {
        cudaStreamCreateWithFlags(&s2, cudaStreamNonBlocking);
        cudaEventCreateWithFlags(&ev_fork, cudaEventDisableTiming);
        cudaEventCreateWithFlags(&ev_join, cudaEventDisableTiming);
    }

    bool full = out_size >= (HID_ELEMS + PB_ELEMS + 8);
    float* out_pb     = out + HID_ELEMS;
    float* out_remain = out + HID_ELEMS + PB_ELEMS;

    cudaEventRecord(ev_fork, 0);
    cudaStreamWaitEvent(s2, ev_fork, 0);
    bias_fill_kernel<<<128, 256, 0, s2>>>(table, full ? out_remain : nullptr);
    if (full) pb_write_kernel<<<dim3(SEQ, NH), 256, 0, s2>>>(out_pb);
    cudaEventRecord(ev_join, s2);

    split_w_kernel<<<4*WELEMS/256, 256>>>(wq, wk, wv, wo);
    split_a_kernel<<<ROWS, 128>>>(hidden, lnw);

    // QKV: z=0 (Q), z=1 (K) 3-product; z=2 (V) 2-product
    mma_gemm_kernel<<<dim3(DM/64, ROWS/128, 3), 256, G_DSM>>>(
        mAh, mAl, mWh, mWl, 0, 0b011, nullptr, pqh, pql, (long long)HID_ELEMS, nullptr, 1);

    cudaStreamWaitEvent(0, ev_join, 0);

    attn_mma_kernel<<<dim3(SEQ/128, NH, NBATCH), 256, ATT_DSM>>>(
        mQh, mQl, pqh, pql, pahi, palo, pbias2);

    // out projection: 2-product + residual
    mma_gemm_kernel<<<dim3(DM/64, ROWS/128, 1), 256, G_DSM>>>(
        mAh, mAl, mWh, mWl, 3, 0, out, nullptr, nullptr, 0, hidden, 0);
}

// round 17
// speedup vs baseline: 1.2572x; 1.0496x over previous
#include <cuda_runtime.h>
#include <cuda.h>
#include <cuda_fp16.h>

#define NBATCH 8
#define SEQ 2048
#define DM 512
#define NH 8
#define DKV 64
#define ROWS (NBATCH*SEQ)
#define HID_ELEMS (ROWS*DM)
#define PB_ELEMS (NH*SEQ*SEQ)
#define WELEMS (DM*DM)
#define LOG2E 1.4426950408889634f

__device__ float g_bias[NH*4096];
__device__ float g_bias2[NH*4096];
__device__ __half g_ahi[HID_ELEMS];
__device__ __half g_alo[HID_ELEMS];
__device__ __half g_whi[4*WELEMS];    // [z][k][n]
__device__ __half g_wlo[4*WELEMS];
__device__ __half g_qkvh[3*HID_ELEMS];
__device__ __half g_qkvl[3*HID_ELEMS];

// ---------------- helpers ----------------
__device__ __forceinline__ unsigned smem_u32(const void* p) {
    unsigned a;
    asm("{ .reg .u64 t; cvta.to.shared.u64 t, %1; cvt.u32.u64 %0, t; }" : "=r"(a) : "l"(p));
    return a;
}
__device__ __forceinline__ unsigned sw128(unsigned x) { return x ^ ((x >> 3) & 0x70u); }
__device__ __forceinline__ void ldsm4(unsigned* r, unsigned addr) {
    asm volatile("ldmatrix.sync.aligned.m8n8.x4.shared.b16 {%0,%1,%2,%3}, [%4];"
        : "=r"(r[0]), "=r"(r[1]), "=r"(r[2]), "=r"(r[3]) : "r"(addr));
}
__device__ __forceinline__ void ldsm4t(unsigned* r, unsigned addr) {
    asm volatile("ldmatrix.sync.aligned.m8n8.x4.trans.shared.b16 {%0,%1,%2,%3}, [%4];"
        : "=r"(r[0]), "=r"(r[1]), "=r"(r[2]), "=r"(r[3]) : "r"(addr));
}
__device__ __forceinline__ void mma16816(float* c, const unsigned* a, unsigned b0, unsigned b1) {
    asm volatile("mma.sync.aligned.m16n8k16.row.col.f32.f16.f16.f32 "
        "{%0,%1,%2,%3}, {%4,%5,%6,%7}, {%8,%9}, {%0,%1,%2,%3};"
        : "+f"(c[0]), "+f"(c[1]), "+f"(c[2]), "+f"(c[3])
        : "r"(a[0]), "r"(a[1]), "r"(a[2]), "r"(a[3]), "r"(b0), "r"(b1));
}
__device__ __forceinline__ void tma2(unsigned dst, const CUtensorMap* m, int x, int y, unsigned mbar) {
    asm volatile("cp.async.bulk.tensor.2d.shared::cta.global.tile.mbarrier::complete_tx::bytes "
        "[%0], [%1, {%2, %3}], [%4];" :: "r"(dst), "l"(m), "r"(x), "r"(y), "r"(mbar) : "memory");
}
#define MBAR_INIT(a,c)   asm volatile("mbarrier.init.shared.b64 [%0], %1;" :: "r"((unsigned)(a)), "r"((unsigned)(c)) : "memory")
#define MBAR_EXPECT(a,b) asm volatile("mbarrier.arrive.expect_tx.shared.b64 _, [%0], %1;" :: "r"((unsigned)(a)), "r"((unsigned)(b)) : "memory")
__device__ __forceinline__ void mbar_wait(unsigned a, unsigned p) {
    asm volatile("{\n\t.reg .pred P;\n\tWL%=:\n\t"
        "mbarrier.try_wait.parity.acquire.cta.shared::cta.b64 P, [%0], %1, 0x989680;\n\t"
        "@P bra.uni WD%=;\n\tbra.uni WL%=;\n\tWD%=:\n\t}" :: "r"(a), "r"(p) : "memory");
}
__device__ __forceinline__ unsigned pack_f16x2(float a, float b) {
    __half2 h = __floats2half2_rn(a, b);
    return *(unsigned*)&h;
}
__device__ __forceinline__ void split2(float a, float b, unsigned& uh, unsigned& ul) {
    __half ha = __float2half_rn(a), hb = __float2half_rn(b);
    unsigned sa = __half_as_ushort(ha), sb_ = __half_as_ushort(hb);
    uh = sa | (sb_ << 16);
    ul = pack_f16x2(a - __half2float(ha), b - __half2float(hb));
}
// exp2 on the (otherwise idle) MUFU pipe. Args are <= 0 after online max;
// ex2.approx flushes very negative args to 0, which is exactly what we want.
__device__ __forceinline__ float ex2(float y) {
    float r;
    asm("ex2.approx.f32 %0, %1;" : "=f"(r) : "f"(y));
    return r;
}

// ---------------- small kernels ----------------
__global__ void bias_fill_kernel(const float* __restrict__ table, float* __restrict__ out_remain) {
    int idx = blockIdx.x * blockDim.x + threadIdx.x;
    if (idx < NH * 4096) {
        int h = idx >> 12;
        int rel = (idx & 4095) - 2047;
        int a = rel < 0 ? -rel : rel;
        int b;
        if (a < 8) b = a;
        else {
            int e = 28 - __clz(a);
            long long aa = (long long)a * (long long)a;
            b = 8 + 2*e + ((aa >= (1LL << (2*e + 7))) ? 1 : 0);
            if (b > 15) b = 15;
        }
        int bucket = (rel > 0 ? 16 : 0) + b;
        float val = table[bucket * NH + h];
        g_bias[idx] = val;
        g_bias2[idx] = val * LOG2E;
    }
    if (out_remain != nullptr && idx < 8) out_remain[idx] = (float)idx;
}

__global__ void pb_write_kernel(float* __restrict__ out_pb) {
    int q = blockIdx.x, h = blockIdx.y;
    const float* brow = g_bias + h * 4096 + (2047 - q);
    float* dst = out_pb + ((size_t)(h * SEQ + q)) * SEQ;
    int t = threadIdx.x;
    #pragma unroll
    for (int it = 0; it < 2; it++) {
        int k4 = (t + it * 256) * 4;
        *(float4*)&dst[k4] = make_float4(brow[k4], brow[k4+1], brow[k4+2], brow[k4+3]);
    }
}

__global__ void split_w_kernel(const float* __restrict__ wq, const float* __restrict__ wk,
                               const float* __restrict__ wv, const float* __restrict__ wo) {
    int idx = blockIdx.x * 256 + threadIdx.x;
    const float* src = (idx < WELEMS) ? wq : (idx < 2*WELEMS) ? wk : (idx < 3*WELEMS) ? wv : wo;
    float x = src[idx & (WELEMS - 1)];
    __half h = __float2half_rn(x);
    g_whi[idx] = h;
    g_wlo[idx] = __float2half_rn(x - __half2float(h));
}

__global__ void split_a_kernel(const float* __restrict__ hidden, const float* __restrict__ lnw) {
    int m = blockIdx.x, t = threadIdx.x;
    float4 v = *(const float4*)&hidden[(size_t)m * DM + t * 4];
    float s = v.x*v.x + v.y*v.y + v.z*v.z + v.w*v.w;
    #pragma unroll
    for (int off = 16; off > 0; off >>= 1) s += __shfl_xor_sync(0xffffffffu, s, off);
    __shared__ float ws[4];
    if ((t & 31) == 0) ws[t >> 5] = s;
    __syncthreads();
    float rms = rsqrtf((ws[0]+ws[1]+ws[2]+ws[3]) * (1.0f/(float)DM) + 1e-6f);
    float4 l = *(const float4*)&lnw[t * 4];
    float a0 = v.x*l.x*rms, a1 = v.y*l.y*rms, a2 = v.z*l.z*rms, a3 = v.w*l.w*rms;
    unsigned uh0, ul0, uh1, ul1;
    split2(a0, a1, uh0, ul0);
    split2(a2, a3, uh1, ul1);
    *(uint2*)&g_ahi[(size_t)m * DM + t * 4] = make_uint2(uh0, uh1);
    *(uint2*)&g_alo[(size_t)m * DM + t * 4] = make_uint2(ul0, ul1);
}

// ---------------------------------------------------------------------------
// fp16 error-split mma.sync GEMM, TMA-fed 2-stage pipeline.
// prod3_mask bit z: 1 -> 3 products, 0 -> 2 products (A full x W-hi).
// ---------------------------------------------------------------------------
#define G_STG 49152u
#define G_DSM (2*49152 + 1024)

__global__ __launch_bounds__(256) void mma_gemm_kernel(
    const __grid_constant__ CUtensorMap mAh, const __grid_constant__ CUtensorMap mAl,
    const __grid_constant__ CUtensorMap mWh, const __grid_constant__ CUtensorMap mWl,
    int wbase, int prod3_mask, float* __restrict__ DstF,
    __half* __restrict__ DstH, __half* __restrict__ DstL,
    long long dzs, const float* __restrict__ resid, int qkv_mode)
{
    extern __shared__ char gsm[];
    __shared__ __align__(8) unsigned long long mb[2];
    unsigned sb = (smem_u32(gsm) + 1023u) & ~1023u;
    int t = threadIdx.x, w = t >> 5, lane = t & 31;
    int n0 = blockIdx.x * 64, m0 = blockIdx.y * 128, z = blockIdx.z;
    int wm = (w >> 1) * 32, wn = (w & 1) * 32;
    int wr = (wbase + z) * DM;
    bool p3 = (prod3_mask >> z) & 1;

    float c[2][4][4];
    #pragma unroll
    for (int i = 0; i < 2; i++)
        #pragma unroll
        for (int j = 0; j < 4; j++)
            #pragma unroll
            for (int k = 0; k < 4; k++) c[i][j][k] = 0.0f;

    int lrowA = lane & 15, lkA = (lane >> 4) * 8;
    int lkB = (lane & 7) + ((lane & 8) ? 8 : 0);
    int lnB = (lane & 16) ? 8 : 0;

    if (t == 0) { MBAR_INIT(smem_u32(&mb[0]), 1); MBAR_INIT(smem_u32(&mb[1]), 1); }
    __syncthreads();
    if (t == 0) {
        unsigned m0b = smem_u32(&mb[0]);
        MBAR_EXPECT(m0b, G_STG);
        tma2(sb,         &mAh, 0, m0, m0b);
        tma2(sb + 16384, &mAl, 0, m0, m0b);
        tma2(sb + 32768, &mWh, n0, wr, m0b);
        tma2(sb + 40960, &mWl, n0, wr, m0b);
    }
    int ph[2] = {0, 0};
    for (int s = 0; s < 8; s++) {
        int b = s & 1;
        unsigned st = sb + (unsigned)b * G_STG;
        if (s + 1 < 8 && t == 0) {
            unsigned sn = sb + (unsigned)(b ^ 1) * G_STG;
            unsigned mbn = smem_u32(&mb[b ^ 1]);
            MBAR_EXPECT(mbn, G_STG);
            tma2(sn,         &mAh, (s+1)*64, m0, mbn);
            tma2(sn + 16384, &mAl, (s+1)*64, m0, mbn);
            tma2(sn + 32768, &mWh, n0, wr + (s+1)*64, mbn);
            tma2(sn + 40960, &mWl, n0, wr + (s+1)*64, mbn);
        }
        mbar_wait(smem_u32(&mb[b]), ph[b]); ph[b] ^= 1;

        #pragma unroll
        for (int kk = 0; kk < 64; kk += 16) {
            unsigned ah[2][4], al[2][4], bh[2][4], bl[2][4];
            #pragma unroll
            for (int mf = 0; mf < 2; mf++) {
                unsigned sa = sw128((unsigned)((wm + mf*16 + lrowA)*128 + (kk + lkA)*2));
                ldsm4(ah[mf], st + sa);
                ldsm4(al[mf], st + 16384 + sa);
            }
            #pragma unroll
            for (int nh = 0; nh < 2; nh++) {
                unsigned sa = sw128((unsigned)((kk + lkB)*128 + (wn + nh*16 + lnB)*2));
                ldsm4t(bh[nh], st + 32768 + sa);
                if (p3) ldsm4t(bl[nh], st + 40960 + sa);
            }
            #pragma unroll
            for (int mf = 0; mf < 2; mf++)
                #pragma unroll
                for (int nf = 0; nf < 4; nf++) {
                    unsigned b0h = bh[nf >> 1][(nf & 1)*2], b1h = bh[nf >> 1][(nf & 1)*2 + 1];
                    mma16816(c[mf][nf], ah[mf], b0h, b1h);
                    mma16816(c[mf][nf], al[mf], b0h, b1h);
                    if (p3) {
                        unsigned b0l = bl[nf >> 1][(nf & 1)*2], b1l = bl[nf >> 1][(nf & 1)*2 + 1];
                        mma16816(c[mf][nf], ah[mf], b0l, b1l);
                    }
                }
        }
        __syncthreads();
    }

    int g = lane >> 2, tc = (lane & 3) * 2;
    float sc = (qkv_mode && z == 0) ? LOG2E : 1.0f;
    #pragma unroll
    for (int mf = 0; mf < 2; mf++)
        #pragma unroll
        for (int nf = 0; nf < 4; nf++) {
            int row = m0 + wm + mf*16 + g;
            int col = n0 + wn + nf*8 + tc;
            float v0 = c[mf][nf][0]*sc, v1 = c[mf][nf][1]*sc;
            float v2 = c[mf][nf][2]*sc, v3 = c[mf][nf][3]*sc;
            if (DstF) {
                if (resid) {
                    float2 r0 = *(const float2*)&resid[(size_t)row*DM + col];
                    float2 r1 = *(const float2*)&resid[(size_t)(row+8)*DM + col];
                    v0 += r0.x; v1 += r0.y; v2 += r1.x; v3 += r1.y;
                }
                *(float2*)&DstF[(size_t)row*DM + col] = make_float2(v0, v1);
                *(float2*)&DstF[(size_t)(row+8)*DM + col] = make_float2(v2, v3);
            } else {
                size_t zo = (size_t)z * dzs;
                unsigned uh, ul;
                split2(v0, v1, uh, ul);
                *(unsigned*)&DstH[zo + (size_t)row*DM + col] = uh;
                *(unsigned*)&DstL[zo + (size_t)row*DM + col] = ul;
                split2(v2, v3, uh, ul);
                *(unsigned*)&DstH[zo + (size_t)(row+8)*DM + col] = uh;
                *(unsigned*)&DstL[zo + (size_t)(row+8)*DM + col] = ul;
            }
        }
}

// ---------------------------------------------------------------------------
// Flash attention, TMA-fed, fp16, online max in log2 domain (P in (0,1]),
// exponentials on the MUFU pipe (ex2.approx) to unload the FMA pipe.
// S = QK^T 3-product; PV single product. Stage = 24KB.
// ---------------------------------------------------------------------------
#define ATT_STG 24576u
#define ATT_DSM (49152 + 1536 + 1024)

__global__ __launch_bounds__(256) void attn_mma_kernel(
    const __grid_constant__ CUtensorMap mH, const __grid_constant__ CUtensorMap mL,
    const __half* __restrict__ Qh, const __half* __restrict__ Ql,
    __half* __restrict__ Chi, __half* __restrict__ Clo,
    const float* __restrict__ Bias2)
{
    extern __shared__ char dyns[];
    __shared__ __align__(8) unsigned long long mb[2];
    unsigned sb = (smem_u32(dyns) + 1023u) & ~1023u;
    char* ab = dyns + (sb - smem_u32(dyns));
    float* sB = (float*)(ab + 49152);

    int t = threadIdx.x, w = t >> 5, lane = t & 31;
    int g = lane >> 2, cq = lane & 3;
    int q0 = blockIdx.x * 128, h = blockIdx.y, n = blockIdx.z;
    size_t base = ((size_t)n * SEQ) * DM + h * DKV;
    const float* brow = Bias2 + h * 4096;

    if (t == 0) { MBAR_INIT(smem_u32(&mb[0]), 1); MBAR_INIT(smem_u32(&mb[1]), 1); }

    {   // Q prologue into stage area (consumed before first prefetch)
        __half* Qs_h = (__half*)ab;
        __half* Qs_l = (__half*)(ab + 18432);
        #pragma unroll
        for (int it = 0; it < 4; it++) {
            int slot = t + 256*it;
            int row = slot >> 3, c8 = (slot & 7) * 8;
            *(uint4*)&Qs_h[row*72 + c8] = *(const uint4*)&Qh[base + (size_t)(q0+row)*DM + c8];
            *(uint4*)&Qs_l[row*72 + c8] = *(const uint4*)&Ql[base + (size_t)(q0+row)*DM + c8];
        }
    }
    __syncthreads();
    unsigned qfh[4][4], qfl[4][4];
    #pragma unroll
    for (int kk = 0; kk < 4; kk++) {
        unsigned addr = (unsigned)((16*w + (lane & 15))*72 + 16*kk + ((lane >> 4)*8)) * 2;
        ldsm4(qfh[kk], sb + addr);
        ldsm4(qfl[kk], sb + 18432 + addr);
    }
    __syncthreads();

    float O[8][4];
    #pragma unroll
    for (int j = 0; j < 8; j++)
        #pragma unroll
        for (int e = 0; e < 4; e++) O[j][e] = 0.0f;
    float lac0 = 0.0f, lac1 = 0.0f;
    float mr0 = -1e30f, mr1 = -1e30f;   // running row max (log2 domain)

    int yK = ROWS + n*SEQ;
    if (t == 0) {
        unsigned m0b = smem_u32(&mb[0]);
        MBAR_EXPECT(m0b, ATT_STG);
        tma2(sb,         &mH, h*64, yK, m0b);
        tma2(sb + 8192,  &mL, h*64, yK, m0b);
        tma2(sb + 16384, &mH, h*64, yK + ROWS, m0b);
    }
    if (t < 192) sB[t] = brow[0 - q0 + 1920 + t];
    __syncthreads();

    int ph[2] = {0, 0};
    const int NB = SEQ / 64;
    int r0 = 16*w + g;
    for (int kb = 0; kb < NB; kb++) {
        int st = kb & 1;
        unsigned stc = sb + (unsigned)st * ATT_STG;
        if (kb + 1 < NB) {
            if (t == 0) {
                unsigned stn = sb + (unsigned)(st ^ 1) * ATT_STG;
                unsigned mbn = smem_u32(&mb[st ^ 1]);
                MBAR_EXPECT(mbn, ATT_STG);
                int y = yK + (kb+1)*64;
                tma2(stn,         &mH, h*64, y, mbn);
                tma2(stn + 8192,  &mL, h*64, y, mbn);
                tma2(stn + 16384, &mH, h*64, y + ROWS, mbn);
            }
            if (t < 192) sB[(st^1)*192 + t] = brow[(kb+1)*64 - q0 + 1920 + t];
        }
        mbar_wait(smem_u32(&mb[st]), ph[st]); ph[st] ^= 1;
        const float* sBc = sB + st*192;

        // ---- S = Q K^T (fp16 3-product) ----
        float S[8][4];
        #pragma unroll
        for (int j = 0; j < 8; j++)
            #pragma unroll
            for (int e = 0; e < 4; e++) S[j][e] = 0.0f;

        #pragma unroll
        for (int kk = 0; kk < 4; kk++) {
            #pragma unroll
            for (int u = 0; u < 4; u++) {
                unsigned bh[4], bl[4];
                unsigned sa = sw128((unsigned)((16*u + (lane & 7) + ((lane & 16) ? 8 : 0))*128
                                               + 32*kk + ((lane & 8) ? 16 : 0)));
                ldsm4(bh, stc + sa);
                ldsm4(bl, stc + 8192 + sa);
                #pragma unroll
                for (int jj = 0; jj < 2; jj++) {
                    int j = 2*u + jj;
                    mma16816(S[j], qfh[kk], bh[2*jj], bh[2*jj+1]);
                    mma16816(S[j], qfl[kk], bh[2*jj], bh[2*jj+1]);
                    mma16816(S[j], qfh[kk], bl[2*jj], bl[2*jj+1]);
                }
            }
        }

        // ---- bias + block-row max + online rescale (log2 domain) ----
        float bm0 = -1e30f, bm1 = -1e30f;
        #pragma unroll
        for (int j = 0; j < 8; j++) {
            int col = 8*j + 2*cq;
            S[j][0] += sBc[col     - r0 + 127];
            S[j][1] += sBc[col + 1 - r0 + 127];
            S[j][2] += sBc[col     - r0 + 119];
            S[j][3] += sBc[col + 1 - r0 + 119];
            bm0 = fmaxf(bm0, fmaxf(S[j][0], S[j][1]));
            bm1 = fmaxf(bm1, fmaxf(S[j][2], S[j][3]));
        }
        bm0 = fmaxf(bm0, __shfl_xor_sync(0xffffffffu, bm0, 1));
        bm0 = fmaxf(bm0, __shfl_xor_sync(0xffffffffu, bm0, 2));
        bm1 = fmaxf(bm1, __shfl_xor_sync(0xffffffffu, bm1, 1));
        bm1 = fmaxf(bm1, __shfl_xor_sync(0xffffffffu, bm1, 2));
        float nm0 = fmaxf(mr0, bm0), nm1 = fmaxf(mr1, bm1);
        float al0 = ex2(mr0 - nm0), al1 = ex2(mr1 - nm1);
        mr0 = nm0; mr1 = nm1;
        lac0 *= al0; lac1 *= al1;
        #pragma unroll
        for (int j = 0; j < 8; j++) {
            O[j][0] *= al0; O[j][1] *= al0;
            O[j][2] *= al1; O[j][3] *= al1;
        }

        // ---- interleaved: MUFU ex2 + pack, then single-product PV ----
        #pragma unroll
        for (int kkk = 0; kkk < 4; kkk++) {
            unsigned aP4[4];
            #pragma unroll
            for (int jj = 0; jj < 2; jj++) {
                int j = 2*kkk + jj;
                float p0 = ex2(S[j][0] - mr0);
                float p1 = ex2(S[j][1] - mr0);
                float p2 = ex2(S[j][2] - mr1);
                float p3 = ex2(S[j][3] - mr1);
                lac0 += p0 + p1;
                lac1 += p2 + p3;
                aP4[jj*2    ] = pack_f16x2(p0, p1);
                aP4[jj*2 + 1] = pack_f16x2(p2, p3);
            }
            #pragma unroll
            for (int u2 = 0; u2 < 4; u2++) {
                unsigned bh[4];
                unsigned sa = sw128((unsigned)((16*kkk + (lane & 7) + ((lane & 8) ? 8 : 0))*128
                                               + 32*u2 + ((lane & 16) ? 16 : 0)));
                ldsm4t(bh, stc + 16384 + sa);
                #pragma unroll
                for (int jj = 0; jj < 2; jj++) {
                    int j = 2*u2 + jj;
                    mma16816(O[j], aP4, bh[2*jj], bh[2*jj+1]);
                }
            }
        }
        __syncthreads();
    }

    lac0 += __shfl_xor_sync(0xffffffffu, lac0, 1);
    lac0 += __shfl_xor_sync(0xffffffffu, lac0, 2);
    lac1 += __shfl_xor_sync(0xffffffffu, lac1, 1);
    lac1 += __shfl_xor_sync(0xffffffffu, lac1, 2);
    float li0 = 1.0f / lac0, li1 = 1.0f / lac1;

    size_t rowA = base + (size_t)(q0 + 16*w + g) * DM;
    size_t rowB = base + (size_t)(q0 + 16*w + g + 8) * DM;
    #pragma unroll
    for (int j = 0; j < 8; j++) {
        int col = 8*j + 2*cq;
        unsigned uh, ul;
        split2(O[j][0] * li0, O[j][1] * li0, uh, ul);
        *(unsigned*)&Chi[rowA + col] = uh;
        *(unsigned*)&Clo[rowA + col] = ul;
        split2(O[j][2] * li1, O[j][3] * li1, uh, ul);
        *(unsigned*)&Chi[rowB + col] = uh;
        *(unsigned*)&Clo[rowB + col] = ul;
    }
}

// ---------------------------------------------------------------------------
typedef CUresult (*EncodeFn)(CUtensorMap*, CUtensorMapDataType, cuuint32_t, void*,
    const cuuint64_t*, const cuuint64_t*, const cuuint32_t*, const cuuint32_t*,
    CUtensorMapInterleave, CUtensorMapSwizzle, CUtensorMapL2promotion, CUtensorMapFloatOOBfill);

static void mk_map(CUtensorMap* m, void* p, unsigned long long inner, unsigned long long outer,
                   unsigned bx, unsigned by) {
    static EncodeFn fn = nullptr;
    if (!fn) {
        cudaDriverEntryPointQueryResult qr;
        cudaGetDriverEntryPointByVersion("cuTensorMapEncodeTiled", (void**)&fn, 12000,
                                         cudaEnableDefault, &qr);
    }
    cuuint64_t d[2] = {inner, outer}, s[1] = {inner * 2};
    cuuint32_t b[2] = {bx, by}, e[2] = {1, 1};
    fn(m, CU_TENSOR_MAP_DATA_TYPE_FLOAT16, 2, p, d, s, b, e,
       CU_TENSOR_MAP_INTERLEAVE_NONE, CU_TENSOR_MAP_SWIZZLE_128B,
       CU_TENSOR_MAP_L2_PROMOTION_L2_128B, CU_TENSOR_MAP_FLOAT_OOB_FILL_NONE);
}

extern "C" void kernel_launch(void* const* d_in, const int* in_sizes, int n_in,
                              void* d_out, int out_size) {
    const float* hidden = (const float*)d_in[0];
    const float* lnw    = (const float*)d_in[1];
    const float* wq     = (const float*)d_in[2];
    const float* wk     = (const float*)d_in[3];
    const float* wv     = (const float*)d_in[4];
    const float* wo     = (const float*)d_in[5];
    const float* table  = (const float*)d_in[6];
    float* out = (float*)d_out;

    float *pbias2;
    __half *pahi, *palo, *pwhi, *pwlo, *pqh, *pql;
    cudaGetSymbolAddress((void**)&pbias2, g_bias2);
    cudaGetSymbolAddress((void**)&pahi,   g_ahi);
    cudaGetSymbolAddress((void**)&palo,   g_alo);
    cudaGetSymbolAddress((void**)&pwhi,   g_whi);
    cudaGetSymbolAddress((void**)&pwlo,   g_wlo);
    cudaGetSymbolAddress((void**)&pqh,    g_qkvh);
    cudaGetSymbolAddress((void**)&pql,    g_qkvl);

    CUtensorMap mAh, mAl, mWh, mWl, mQh, mQl;
    mk_map(&mAh, pahi, DM, ROWS,   64, 128);
    mk_map(&mAl, palo, DM, ROWS,   64, 128);
    mk_map(&mWh, pwhi, DM, 4*DM,   64, 64);
    mk_map(&mWl, pwlo, DM, 4*DM,   64, 64);
    mk_map(&mQh, pqh,  DM, 3*ROWS, 64, 64);
    mk_map(&mQl, pql,  DM, 3*ROWS, 64, 64);

    cudaFuncSetAttribute(attn_mma_kernel, cudaFuncAttributeMaxDynamicSharedMemorySize, ATT_DSM);
    cudaFuncSetAttribute(mma_gemm_kernel, cudaFuncAttributeMaxDynamicSharedMemorySize, G_DSM);

    static cudaStream_t s2 = nullptr;
    static cudaEvent_t ev_fork = nullptr, ev_join = nullptr;
    if (s2 == nullptr) {
        cudaStreamCreateWithFlags(&s2, cudaStreamNonBlocking);
        cudaEventCreateWithFlags(&ev_fork, cudaEventDisableTiming);
        cudaEventCreateWithFlags(&ev_join, cudaEventDisableTiming);
    }

    bool full = out_size >= (HID_ELEMS + PB_ELEMS + 8);
    float* out_pb     = out + HID_ELEMS;
    float* out_remain = out + HID_ELEMS + PB_ELEMS;

    cudaEventRecord(ev_fork, 0);
    cudaStreamWaitEvent(s2, ev_fork, 0);
    bias_fill_kernel<<<128, 256, 0, s2>>>(table, full ? out_remain : nullptr);
    if (full) pb_write_kernel<<<dim3(SEQ, NH), 256, 0, s2>>>(out_pb);
    cudaEventRecord(ev_join, s2);

    split_w_kernel<<<4*WELEMS/256, 256>>>(wq, wk, wv, wo);
    split_a_kernel<<<ROWS, 128>>>(hidden, lnw);

    // QKV: z=0 (Q), z=1 (K) 3-product; z=2 (V) 2-product
    mma_gemm_kernel<<<dim3(DM/64, ROWS/128, 3), 256, G_DSM>>>(
        mAh, mAl, mWh, mWl, 0, 0b011, nullptr, pqh, pql, (long long)HID_ELEMS, nullptr, 1);

    cudaStreamWaitEvent(0, ev_join, 0);

    attn_mma_kernel<<<dim3(SEQ/128, NH, NBATCH), 256, ATT_DSM>>>(
        mQh, mQl, pqh, pql, pahi, palo, pbias2);

    // out projection: 2-product + residual
    mma_gemm_kernel<<<dim3(DM/64, ROWS/128, 1), 256, G_DSM>>>(
        mAh, mAl, mWh, mWl, 3, 0, out, nullptr, nullptr, 0, hidden, 0);
}